// round 4
// baseline (speedup 1.0000x reference)
#include <cuda_runtime.h>
#include <cuda_bf16.h>
#include <cstdint>

// ===================== problem constants =====================
constexpr int T  = 4096;
constexpr int E  = 1024;
constexpr int MH = 512;      // E/2
constexpr int BB = 4;
constexpr int NC = BB * MH;  // 2048 GEMM columns
constexpr float EPSF = 1e-6f;

// ===================== device scratch (no allocs allowed) =====================
__device__ __nv_bfloat16 g_K [(size_t)T * T];   // 32 MB normalized kernel, bf16
__device__ __nv_bfloat16 g_Xt[(size_t)NC * T];  // 16 MB (x_c * gate)^T, K-major
__device__ float         g_gate[MH];

// ===================== PTX helpers (baseline ISA only: sm_80-era) =====================
__device__ __forceinline__ uint32_t smem_u32(const void* p) {
    uint32_t a;
    asm("{ .reg .u64 t; cvta.to.shared.u64 t, %1; cvt.u32.u64 %0, t; }" : "=r"(a) : "l"(p));
    return a;
}

__device__ __forceinline__ void cp_async16(uint32_t smem, const void* gmem) {
    asm volatile("cp.async.cg.shared.global [%0], [%1], 16;" :: "r"(smem), "l"(gmem));
}
__device__ __forceinline__ void cp_commit() {
    asm volatile("cp.async.commit_group;" ::: "memory");
}
template<int N> __device__ __forceinline__ void cp_wait() {
    asm volatile("cp.async.wait_group %0;" :: "n"(N) : "memory");
}

__device__ __forceinline__ void ldsm4(uint32_t* r, uint32_t addr) {
    asm volatile("ldmatrix.sync.aligned.m8n8.x4.shared.b16 {%0,%1,%2,%3}, [%4];"
                 : "=r"(r[0]), "=r"(r[1]), "=r"(r[2]), "=r"(r[3]) : "r"(addr));
}

__device__ __forceinline__ void mma16816(float* c, const uint32_t* a, uint32_t b0, uint32_t b1) {
    asm volatile("mma.sync.aligned.m16n8k16.row.col.f32.bf16.bf16.f32 "
                 "{%0,%1,%2,%3}, {%4,%5,%6,%7}, {%8,%9}, {%0,%1,%2,%3};"
                 : "+f"(c[0]), "+f"(c[1]), "+f"(c[2]), "+f"(c[3])
                 : "r"(a[0]), "r"(a[1]), "r"(a[2]), "r"(a[3]), "r"(b0), "r"(b1));
}

// smem tile layout: logical 128 rows x 64B (32 bf16). Two logical rows packed per
// 128B physical row; 16B chunk index XOR-swizzled by physical row (mod 8).
// Conflict-free for 8-row ldmatrix phases.
__device__ __forceinline__ uint32_t swoff(int r, int c) {
    int p   = r >> 1;
    int idx = ((r & 1) << 2) | c;          // 0..7 16B chunk within 128B row
    return (uint32_t)((p << 7) | ((idx ^ (p & 7)) << 4));
}

// ===================== prep kernels =====================
__global__ void build_gate_kernel(const float* __restrict__ graw) {
    int i = threadIdx.x;
    if (i < MH) g_gate[i] = log1pf(__expf(graw[i]));
}

// one block per row i: compute unnormalized bump row (zeros for j<i), reduce, normalize, bf16
__global__ __launch_bounds__(256) void build_K_kernel() {
    __shared__ float rowv[T];
    __shared__ float red[8];
    int i = blockIdx.x;
    int tid = threadIdx.x;
    float inv_n = 1.0f / (float)((T - i) > 1 ? (T - i) : 1);
    float acc = 0.0f;
    for (int j = tid; j < T; j += 256) {
        float v = 0.0f;
        if (j >= i) {
            float u = fminf((float)(j - i) * inv_n, 1.0f - EPSF);
            float den = 1.0f - u * u + EPSF;
            v = __expf(1.0f - __fdividef(1.0f, den));
            if (u >= 1.0f - EPSF) v = EPSF;
        }
        rowv[j] = v;
        acc += v;
    }
    #pragma unroll
    for (int o = 16; o; o >>= 1) acc += __shfl_xor_sync(0xFFFFFFFFu, acc, o);
    if ((tid & 31) == 0) red[tid >> 5] = acc;
    __syncthreads();
    if (tid < 8) {
        float a = red[tid];
        #pragma unroll
        for (int o = 4; o; o >>= 1) a += __shfl_xor_sync(0xFFu, a, o);
        if (tid == 0) red[0] = a;
    }
    __syncthreads();
    float inv_s = __fdividef(1.0f, fmaxf(red[0], EPSF));
    for (int j = tid; j < T; j += 256)
        g_K[(size_t)i * T + j] = __float2bfloat16(rowv[j] * inv_s);
}

// Xt[b*512+m][t] = bf16( x[b,t,2m] * gate[m] ) — coalesced transpose through smem
__global__ void build_Xt_kernel(const float* __restrict__ x) {
    __shared__ float tile[32][33];
    int tx = threadIdx.x, ty = threadIdx.y;         // 32 x 8
    int m0 = blockIdx.x * 32, t0 = blockIdx.y * 32, b = blockIdx.z;
    const float* xb = x + (size_t)b * T * E;
    #pragma unroll
    for (int r = 0; r < 4; r++) {
        int row = ty + r * 8;                        // t-local
        tile[row][tx] = xb[(size_t)(t0 + row) * E + 2 * (m0 + tx)];
    }
    __syncthreads();
    #pragma unroll
    for (int r = 0; r < 4; r++) {
        int mm = ty + r * 8;                         // m-local
        float g = g_gate[m0 + mm];
        g_Xt[(size_t)(b * MH + m0 + mm) * T + t0 + tx] =
            __float2bfloat16(tile[tx][mm] * g);
    }
}

// ===================== GEMM + fused epilogue =====================
// CTA tile 128(M=t-out) x 128(N=cols) x K-chunk 32; 8 warps @ 64x32; 3-stage cp.async.
constexpr int STAGES   = 3;
constexpr int STAGE_B  = 16384;          // 8KB A + 8KB B per stage
constexpr int NKCH     = T / 32;         // 128 k-chunks

__global__ __launch_bounds__(256, 2) void gemm_kernel(const float* __restrict__ x,
                                                      float* __restrict__ out) {
    __shared__ char smem[STAGES * STAGE_B];   // 48KB
    uint32_t sb = smem_u32(smem);

    int tid  = threadIdx.x;
    int wid  = tid >> 5;
    int lane = tid & 31;

    int ti = blockIdx.x >> 4;    // 0..31 row tile (t-out) — heavy tiles first
    int tn = blockIdx.x & 15;    // 0..15 col tile
    int tiRow = ti * 128;
    int tnRow = tn * 128;

    // ---- loader setup: thread handles 2 x 16B chunks for A and B each ----
    int rL = tid >> 2, cL = tid & 3;                  // row 0..63, chunk 0..3
    const char* gK = reinterpret_cast<const char*>(g_K);
    const char* gX = reinterpret_cast<const char*>(g_Xt);
    const char* gA0 = gK + ((size_t)(tiRow + rL) * T + cL * 8) * 2;
    const char* gA1 = gA0 + (size_t)64 * T * 2;
    const char* gB0 = gX + ((size_t)(tnRow + rL) * T + cL * 8) * 2;
    const char* gB1 = gB0 + (size_t)64 * T * 2;
    uint32_t swL = swoff(rL, cL);                     // swoff(r+64,c) = swoff(r,c)+4096

    // ---- ldmatrix per-lane smem offsets ----
    int mw = wid & 1;            // warp m: 0/1 -> +0/+64
    int nw = wid >> 1;           // warp n: 0..3 -> +32*nw
    int q  = lane >> 3;
    uint32_t aOff[4][2], bOff[2][2];
    #pragma unroll
    for (int mt = 0; mt < 4; mt++)
        #pragma unroll
        for (int h = 0; h < 2; h++) {
            int row = mw * 64 + mt * 16 + ((q & 1) << 3) + (lane & 7);
            aOff[mt][h] = swoff(row, h * 2 + (q >> 1));
        }
    #pragma unroll
    for (int nt = 0; nt < 2; nt++)
        #pragma unroll
        for (int h = 0; h < 2; h++) {
            int row = nw * 32 + nt * 16 + ((q >> 1) << 3) + (lane & 7);
            bOff[nt][h] = swoff(row, h * 2 + (q & 1));
        }

    float acc[4][4][4];
    #pragma unroll
    for (int i = 0; i < 4; i++)
        #pragma unroll
        for (int j = 0; j < 4; j++)
            #pragma unroll
            for (int k = 0; k < 4; k++) acc[i][j][k] = 0.0f;

    int kk0 = ti * 4;            // triangular skip: K[i,j]=0 for j < 128*ti

    auto issue = [&](int stage, int kk) {
        uint32_t s = sb + stage * STAGE_B;
        size_t g = (size_t)kk * 64;
        cp_async16(s + swL,               gA0 + g);
        cp_async16(s + swL + 4096,        gA1 + g);
        cp_async16(s + 8192 + swL,        gB0 + g);
        cp_async16(s + 8192 + swL + 4096, gB1 + g);
        cp_commit();
    };

    // prologue: prefetch first STAGES-1 chunks
    issue(kk0 % STAGES, kk0);
    issue((kk0 + 1) % STAGES, kk0 + 1);

    for (int kk = kk0; kk < NKCH; kk++) {
        cp_wait<STAGES - 2>();
        __syncthreads();
        int kn = kk + STAGES - 1;
        if (kn < NKCH) issue(kn % STAGES, kn);
        else           cp_commit();                 // keep group accounting aligned

        uint32_t sA = sb + (kk % STAGES) * STAGE_B;
        uint32_t sB = sA + 8192;
        #pragma unroll
        for (int h = 0; h < 2; h++) {
            uint32_t br[2][4];
            ldsm4(br[0], sB + bOff[0][h]);
            ldsm4(br[1], sB + bOff[1][h]);
            #pragma unroll
            for (int mt = 0; mt < 4; mt++) {
                uint32_t ar[4];
                ldsm4(ar, sA + aOff[mt][h]);
                mma16816(acc[mt][0], ar, br[0][0], br[0][1]);
                mma16816(acc[mt][1], ar, br[0][2], br[0][3]);
                mma16816(acc[mt][2], ar, br[1][0], br[1][1]);
                mma16816(acc[mt][3], ar, br[1][2], br[1][3]);
            }
        }
    }

    // ---- fused epilogue: out[...,0::2]=x even (exact), out[...,1::2]=acc ----
    const float4* x4   = reinterpret_cast<const float4*>(x);
    float4*       out4 = reinterpret_cast<float4*>(out);
    int r0    = lane >> 2;
    int cpair = (lane & 3) * 2;
    #pragma unroll
    for (int mt = 0; mt < 4; mt++) {
        int t0 = tiRow + mw * 64 + mt * 16 + r0;
        #pragma unroll
        for (int n8 = 0; n8 < 4; n8++) {
            int n = tnRow + nw * 32 + n8 * 8 + cpair;
            int b = n >> 9;
            int m = n & 511;
            size_t f4 = ((size_t)(b * T + t0) << 8) + (m >> 1);  // 256 float4 per row
            float4 v = x4[f4];
            v.y = acc[mt][n8][0];
            v.w = acc[mt][n8][1];
            out4[f4] = v;
            float4 v2 = x4[f4 + 2048];                           // row t0+8
            v2.y = acc[mt][n8][2];
            v2.w = acc[mt][n8][3];
            out4[f4 + 2048] = v2;
        }
    }
}

// ===================== launch =====================
extern "C" void kernel_launch(void* const* d_in, const int* in_sizes, int n_in,
                              void* d_out, int out_size) {
    const float* x    = (const float*)d_in[0];   // (4,4096,1024) f32
    // d_in[1] = mask (triu, constant) — reproduced analytically
    const float* graw = (const float*)d_in[2];   // (512,) f32
    float* out = (float*)d_out;

    build_gate_kernel<<<1, 512>>>(graw);
    build_K_kernel<<<T, 256>>>();
    dim3 tb(32, 8);
    dim3 tg(MH / 32, T / 32, BB);
    build_Xt_kernel<<<tg, tb>>>(x);
    gemm_kernel<<<512, 256>>>(x, out);
}

// round 5
// speedup vs baseline: 1.1172x; 1.1172x over previous
#include <cuda_runtime.h>
#include <cuda_bf16.h>
#include <cstdint>

// ===================== problem constants =====================
constexpr int T  = 4096;
constexpr int E  = 1024;
constexpr int MH = 512;      // E/2
constexpr int BB = 4;
constexpr int NC = BB * MH;  // 2048 GEMM columns
constexpr float EPSF = 1e-6f;

// ===================== device scratch (no allocs allowed) =====================
__device__ __nv_bfloat16 g_K [(size_t)T * T];   // normalized kernel, bf16 (upper-block region only)
__device__ __nv_bfloat16 g_Xt[(size_t)NC * T];  // (x_c * gate)^T, K-major
__device__ float         g_gate[MH];

// ===================== PTX helpers (baseline ISA only) =====================
__device__ __forceinline__ uint32_t smem_u32(const void* p) {
    uint32_t a;
    asm("{ .reg .u64 t; cvta.to.shared.u64 t, %1; cvt.u32.u64 %0, t; }" : "=r"(a) : "l"(p));
    return a;
}
__device__ __forceinline__ void cp_async16(uint32_t smem, const void* gmem) {
    asm volatile("cp.async.cg.shared.global [%0], [%1], 16;" :: "r"(smem), "l"(gmem));
}
__device__ __forceinline__ void cp_commit() {
    asm volatile("cp.async.commit_group;" ::: "memory");
}
template<int N> __device__ __forceinline__ void cp_wait() {
    asm volatile("cp.async.wait_group %0;" :: "n"(N) : "memory");
}
__device__ __forceinline__ void ldsm4(uint32_t* r, uint32_t addr) {
    asm volatile("ldmatrix.sync.aligned.m8n8.x4.shared.b16 {%0,%1,%2,%3}, [%4];"
                 : "=r"(r[0]), "=r"(r[1]), "=r"(r[2]), "=r"(r[3]) : "r"(addr));
}
__device__ __forceinline__ void mma16816(float* c, const uint32_t* a, uint32_t b0, uint32_t b1) {
    asm volatile("mma.sync.aligned.m16n8k16.row.col.f32.bf16.bf16.f32 "
                 "{%0,%1,%2,%3}, {%4,%5,%6,%7}, {%8,%9}, {%0,%1,%2,%3};"
                 : "+f"(c[0]), "+f"(c[1]), "+f"(c[2]), "+f"(c[3])
                 : "r"(a[0]), "r"(a[1]), "r"(a[2]), "r"(a[3]), "r"(b0), "r"(b1));
}

// ===================== prep kernels =====================
__global__ void build_gate_kernel(const float* __restrict__ graw) {
    int i = threadIdx.x;
    if (i < MH) g_gate[i] = log1pf(__expf(graw[i]));
}

// one block per row i: only j >= (i & ~127) is ever read by the GEMM (k-skip),
// so compute/normalize/write only that region. K[i,j]=0 for j<i inside it.
__global__ __launch_bounds__(256) void build_K_kernel() {
    __shared__ float rowv[T];
    __shared__ float red[8];
    int i = blockIdx.x;
    int tid = threadIdx.x;
    int j0 = i & ~127;
    float inv_n = 1.0f / (float)((T - i) > 1 ? (T - i) : 1);
    float acc = 0.0f;
    for (int j = j0 + tid; j < T; j += 256) {
        float v = 0.0f;
        if (j >= i) {
            float u = fminf((float)(j - i) * inv_n, 1.0f - EPSF);
            float den = 1.0f - u * u + EPSF;
            v = __expf(1.0f - __fdividef(1.0f, den));
            if (u >= 1.0f - EPSF) v = EPSF;
        }
        rowv[j] = v;
        acc += v;
    }
    #pragma unroll
    for (int o = 16; o; o >>= 1) acc += __shfl_xor_sync(0xFFFFFFFFu, acc, o);
    if ((tid & 31) == 0) red[tid >> 5] = acc;
    __syncthreads();
    if (tid < 8) {
        float a = red[tid];
        #pragma unroll
        for (int o = 4; o; o >>= 1) a += __shfl_xor_sync(0xFFu, a, o);
        if (tid == 0) red[0] = a;
    }
    __syncthreads();
    float inv_s = __fdividef(1.0f, fmaxf(red[0], EPSF));
    for (int j = j0 + tid; j < T; j += 256)
        g_K[(size_t)i * T + j] = __float2bfloat16(rowv[j] * inv_s);
}

// Xt[b*512+m][t] = bf16( x[b,t,2m] * gate[m] ) — coalesced transpose through smem
__global__ void build_Xt_kernel(const float* __restrict__ x) {
    __shared__ float tile[32][33];
    int tx = threadIdx.x, ty = threadIdx.y;         // 32 x 8
    int m0 = blockIdx.x * 32, t0 = blockIdx.y * 32, b = blockIdx.z;
    const float* xb = x + (size_t)b * T * E;
    #pragma unroll
    for (int r = 0; r < 4; r++) {
        int row = ty + r * 8;                        // t-local
        tile[row][tx] = xb[(size_t)(t0 + row) * E + 2 * (m0 + tx)];
    }
    __syncthreads();
    #pragma unroll
    for (int r = 0; r < 4; r++) {
        int mm = ty + r * 8;                         // m-local
        float g = g_gate[m0 + mm];
        g_Xt[(size_t)(b * MH + m0 + mm) * T + t0 + tx] =
            __float2bfloat16(tile[tx][mm] * g);
    }
}

// ===================== GEMM + fused epilogue =====================
// CTA tile 128(M) x 128(N), K-chunk 64; 8 warps @ 64x32; 3-stage cp.async (96KB dyn smem).
constexpr int STAGES   = 3;
constexpr int STAGE_B  = 32768;          // 16KB A + 16KB B per stage
constexpr int NKCH     = T / 64;         // 64 k-chunks

// smem tile: 128 rows x 128B; standard SW128 swizzle (16B chunk ^ row%8)
__device__ __forceinline__ uint32_t sw64(int r, int c) {   // c = 16B chunk 0..7
    return (uint32_t)((r << 7) | (((c ^ (r & 7)) & 7) << 4));
}

__global__ __launch_bounds__(256, 2) void gemm_kernel(const float* __restrict__ x,
                                                      float* __restrict__ out) {
    extern __shared__ char smem[];
    uint32_t sb = smem_u32(smem);

    int tid  = threadIdx.x;
    int wid  = tid >> 5;
    int lane = tid & 31;

    int ti = blockIdx.x >> 4;    // 0..31 row tile (heavy first)
    int tn = blockIdx.x & 15;    // 0..15 col tile
    int tiRow = ti * 128;
    int tnRow = tn * 128;

    // ---- loader: thread owns (rL, cL); covers 4 row-groups of 32 via +32 strides ----
    int rL = tid >> 3, cL = tid & 7;                  // row 0..31, chunk 0..7
    const char* gK = reinterpret_cast<const char*>(g_K);
    const char* gX = reinterpret_cast<const char*>(g_Xt);
    const char* gA = gK + ((size_t)(tiRow + rL) * T + cL * 8) * 2;
    const char* gB = gX + ((size_t)(tnRow + rL) * T + cL * 8) * 2;
    uint32_t swL = sw64(rL, cL);                      // +32 rows => +4096B, xor invariant
    constexpr size_t GSTRIDE = (size_t)32 * T * 2;    // 32 rows in gmem

    // ---- ldmatrix per-lane rows (offset computed per h with xor) ----
    int mw = wid & 1;            // warp m: +0/+64
    int nw = wid >> 1;           // warp n: +32*nw
    int q  = lane >> 3;
    int aRow[4], bRow[2];
    #pragma unroll
    for (int mt = 0; mt < 4; mt++) aRow[mt] = mw * 64 + mt * 16 + ((q & 1) << 3) + (lane & 7);
    #pragma unroll
    for (int nt = 0; nt < 2; nt++) bRow[nt] = nw * 32 + nt * 16 + ((q >> 1) << 3) + (lane & 7);
    int aChunkSel = q >> 1;      // +0/+1 16B chunk (k half)
    int bChunkSel = q & 1;

    float acc[4][4][4];
    #pragma unroll
    for (int i = 0; i < 4; i++)
        #pragma unroll
        for (int j = 0; j < 4; j++)
            #pragma unroll
            for (int k = 0; k < 4; k++) acc[i][j][k] = 0.0f;

    int kk0 = ti * 2;            // triangular skip: K[i,j]=0 for j < 128*ti

    auto issue = [&](int stage, int kk) {
        uint32_t s = sb + stage * STAGE_B;
        size_t g = (size_t)kk * 128;                  // 64 bf16 = 128B per row per chunk
        #pragma unroll
        for (int it = 0; it < 4; it++) {
            cp_async16(s + swL + it * 4096,         gA + g + it * GSTRIDE);
            cp_async16(s + 16384 + swL + it * 4096, gB + g + it * GSTRIDE);
        }
        cp_commit();
    };

    issue(kk0 % STAGES, kk0);
    issue((kk0 + 1) % STAGES, kk0 + 1);

    for (int kk = kk0; kk < NKCH; kk++) {
        cp_wait<STAGES - 2>();
        __syncthreads();
        int kn = kk + STAGES - 1;
        if (kn < NKCH) issue(kn % STAGES, kn);
        else           cp_commit();                   // keep group accounting aligned

        uint32_t sA = sb + (kk % STAGES) * STAGE_B;
        uint32_t sB = sA + 16384;
        #pragma unroll
        for (int h = 0; h < 4; h++) {                 // 4 x k16 slices within 64-chunk
            int ca = h * 2 + aChunkSel;
            int cb = h * 2 + bChunkSel;
            uint32_t br[2][4];
            ldsm4(br[0], sB + sw64(bRow[0], cb));
            ldsm4(br[1], sB + sw64(bRow[1], cb));
            #pragma unroll
            for (int mt = 0; mt < 4; mt++) {
                uint32_t ar[4];
                ldsm4(ar, sA + sw64(aRow[mt], ca));
                mma16816(acc[mt][0], ar, br[0][0], br[0][1]);
                mma16816(acc[mt][1], ar, br[0][2], br[0][3]);
                mma16816(acc[mt][2], ar, br[1][0], br[1][1]);
                mma16816(acc[mt][3], ar, br[1][2], br[1][3]);
            }
        }
    }

    // ---- fused epilogue: out even = x even (exact), out odd = acc ----
    const float4* x4   = reinterpret_cast<const float4*>(x);
    float4*       out4 = reinterpret_cast<float4*>(out);
    int r0    = lane >> 2;
    int cpair = (lane & 3) * 2;
    #pragma unroll
    for (int mt = 0; mt < 4; mt++) {
        int t0 = tiRow + mw * 64 + mt * 16 + r0;
        #pragma unroll
        for (int n8 = 0; n8 < 4; n8++) {
            int n = tnRow + nw * 32 + n8 * 8 + cpair;
            int b = n >> 9;
            int m = n & 511;
            size_t f4 = ((size_t)(b * T + t0) << 8) + (m >> 1);  // 256 float4 per row
            float4 v = x4[f4];
            v.y = acc[mt][n8][0];
            v.w = acc[mt][n8][1];
            out4[f4] = v;
            float4 v2 = x4[f4 + 2048];                           // row t0+8
            v2.y = acc[mt][n8][2];
            v2.w = acc[mt][n8][3];
            out4[f4 + 2048] = v2;
        }
    }
}

// ===================== launch =====================
extern "C" void kernel_launch(void* const* d_in, const int* in_sizes, int n_in,
                              void* d_out, int out_size) {
    const float* x    = (const float*)d_in[0];   // (4,4096,1024) f32
    // d_in[1] = mask (triu, constant) — reproduced analytically
    const float* graw = (const float*)d_in[2];   // (512,) f32
    float* out = (float*)d_out;

    cudaFuncSetAttribute(gemm_kernel, cudaFuncAttributeMaxDynamicSharedMemorySize,
                         STAGES * STAGE_B);

    build_gate_kernel<<<1, 512>>>(graw);
    build_K_kernel<<<T, 256>>>();
    dim3 tb(32, 8);
    dim3 tg(MH / 32, T / 32, BB);
    build_Xt_kernel<<<tg, tb>>>(x);
    gemm_kernel<<<512, 256, STAGES * STAGE_B>>>(x, out);
}